// round 1
// baseline (speedup 1.0000x reference)
#include <cuda_runtime.h>
#include <cstdint>

typedef unsigned long long ull;

// ---------------- constants ----------------
#define NDICT   50000
#define DIN     256
#define DH      256
#define NGATE   1024
#define BB      256
#define SS      512
#define NBLK_SCAN 128
// scan smem: hs[256][128] + Us[256][36]
#define HS_FLOATS   (256 * 128)
#define US_PITCH    36
#define SCAN_SMEM   ((HS_FLOATS + 256 * US_PITCH) * 4)

// ---------------- device scratch (static: no allocs allowed) ----------------
__device__ float g_EW[(size_t)NDICT * NGATE];       // Emb@W^T + bias, cols permuted j*4+type (204.8MB)
__device__ float g_h[2 * 2 * DH * BB];              // [buf][dir][hidden j][batch b]
__device__ int   g_wordsT[SS * BB];                 // words transposed [s][b]
__device__ unsigned g_bar;

// ---------------- f32x2 helpers ----------------
__device__ __forceinline__ ull pk(float x, float y) {
    ull r; asm("mov.b64 %0, {%1, %2};" : "=l"(r) : "f"(x), "f"(y)); return r;
}
__device__ __forceinline__ void upk(ull v, float& x, float& y) {
    asm("mov.b64 {%0, %1}, %2;" : "=f"(x), "=f"(y) : "l"(v));
}
__device__ __forceinline__ void fma2(ull& d, ull a, ull b) {
    asm("fma.rn.f32x2 %0, %1, %2, %0;" : "+l"(d) : "l"(a), "l"(b));
}
__device__ __forceinline__ float sigmoidf_(float x) { return 1.0f / (1.0f + expf(-x)); }

// ---------------- kernel 0: reset barrier + transpose words ----------------
__global__ void reset_kernel(const int* __restrict__ words) {
    int idx = blockIdx.x * blockDim.x + threadIdx.x;
    if (idx == 0) g_bar = 0u;
    for (int i = idx; i < SS * BB; i += gridDim.x * blockDim.x) {
        int s = i >> 8, b = i & 255;
        g_wordsT[i] = words[b * SS + s];
    }
}

// ---------------- kernel 1: EW = Emb @ W^T (+bias), columns permuted ----------------
// col' = j*4 + type  <->  gate row grow = type*256 + j
__global__ __launch_bounds__(256) void ew_gemm(const float* __restrict__ Emb,
                                               const float* __restrict__ W,
                                               const float* __restrict__ bias) {
    __shared__ __align__(16) float As[16][68];  // [k][m]
    __shared__ __align__(16) float Bs[16][68];  // [k][n]
    int tid = threadIdx.x;
    int mbase = blockIdx.x * 64;
    int nbase = blockIdx.y * 64;
    int tx = tid & 15, ty = tid >> 4;      // n-quad, m-quad
    int lr = tid >> 2, lk = (tid & 3) * 4; // loader row / k offset

    ull acc[4][2];
#pragma unroll
    for (int r = 0; r < 4; r++) { acc[r][0] = 0ull; acc[r][1] = 0ull; }

    int colp_l = nbase + lr;
    int grow_l = (colp_l & 3) * 256 + (colp_l >> 2);
    int va = mbase + lr;

    for (int kb = 0; kb < DIN; kb += 16) {
        float4 av = make_float4(0.f, 0.f, 0.f, 0.f);
        if (va < NDICT) av = *(const float4*)&Emb[(size_t)va * DIN + kb + lk];
        As[lk + 0][lr] = av.x; As[lk + 1][lr] = av.y;
        As[lk + 2][lr] = av.z; As[lk + 3][lr] = av.w;
        float4 bv = *(const float4*)&W[(size_t)grow_l * DIN + kb + lk];
        Bs[lk + 0][lr] = bv.x; Bs[lk + 1][lr] = bv.y;
        Bs[lk + 2][lr] = bv.z; Bs[lk + 3][lr] = bv.w;
        __syncthreads();
#pragma unroll
        for (int kk = 0; kk < 16; kk++) {
            float4 a = *(float4*)&As[kk][ty * 4];
            float4 b4 = *(float4*)&Bs[kk][tx * 4];
            ull b01 = pk(b4.x, b4.y), b23 = pk(b4.z, b4.w);
            ull h;
            h = pk(a.x, a.x); fma2(acc[0][0], h, b01); fma2(acc[0][1], h, b23);
            h = pk(a.y, a.y); fma2(acc[1][0], h, b01); fma2(acc[1][1], h, b23);
            h = pk(a.z, a.z); fma2(acc[2][0], h, b01); fma2(acc[2][1], h, b23);
            h = pk(a.w, a.w); fma2(acc[3][0], h, b01); fma2(acc[3][1], h, b23);
        }
        __syncthreads();
    }

    int colp0 = nbase + tx * 4;      // multiple of 4 -> types 0..3, j = colp0>>2
    int jj = colp0 >> 2;
    float bi = bias[jj], bf = bias[256 + jj], bo = bias[512 + jj], bc = bias[768 + jj];
#pragma unroll
    for (int r = 0; r < 4; r++) {
        int v = mbase + ty * 4 + r;
        if (v < NDICT) {
            float o0, o1, o2, o3;
            upk(acc[r][0], o0, o1); upk(acc[r][1], o2, o3);
            float4 out = make_float4(o0 + bi, o1 + bf, o2 + bo, o3 + bc);
            *(float4*)&g_EW[(size_t)v * NGATE + colp0] = out;
        }
    }
}

// ---------------- kernel 2: persistent bidirectional LSTM scan ----------------
// grid = 128 CTAs: dir(2) x batch-tile(2, 128 rows) x hidden-slice(32, 8 units)
__global__ __launch_bounds__(256, 1) void scan_kernel(const float* __restrict__ U) {
    extern __shared__ float sm[];
    float* hs = sm;                 // [256][128]  h staged (k-major)
    float* Us = sm + HS_FLOATS;     // [256][36]   U slice (k-major, permuted cols)

    int tid = threadIdx.x;
    int bx = blockIdx.x;
    int dir = bx >> 6;
    int bt  = (bx >> 5) & 1;
    int js  = bx & 31;
    int jbase = js * 8;
    int tx = tid & 7, ty = tid >> 3;
    int tx4 = tx * 4, ty4 = ty * 4;
    int bbase = bt * 128 + ty4;     // first of this thread's 4 batch rows
    int j = jbase + tx;             // this thread's hidden unit

    // preload U slice: Us[k][col] = U[grow(col)][k], col = jl*4+type
    for (int i = tid; i < 32 * 256; i += 256) {
        int col = i >> 8, k = i & 255;
        int type = col & 3, jl = col >> 2;
        Us[k * US_PITCH + col] = U[(size_t)(type * 256 + jbase + jl) * DH + k];
    }

    float c0 = 0.f, c1 = 0.f, c2 = 0.f, c3 = 0.f;
    __syncthreads();

    for (int t = 0; t < SS; t++) {
        int cur = t & 1, nxt = cur ^ 1;
        int s = dir ? (SS - 1 - t) : t;

        // prefetch word rows of EW (xg + bias) for this thread's tile
        int wrd0 = g_wordsT[s * BB + bbase + 0];
        int wrd1 = g_wordsT[s * BB + bbase + 1];
        int wrd2 = g_wordsT[s * BB + bbase + 2];
        int wrd3 = g_wordsT[s * BB + bbase + 3];
        float4 e0 = *(const float4*)&g_EW[(size_t)wrd0 * NGATE + j * 4];
        float4 e1 = *(const float4*)&g_EW[(size_t)wrd1 * NGATE + j * 4];
        float4 e2 = *(const float4*)&g_EW[(size_t)wrd2 * NGATE + j * 4];
        float4 e3 = *(const float4*)&g_EW[(size_t)wrd3 * NGATE + j * 4];

        // stage h(t) [128 rows x 256 hidden] into smem, k-major
        const float* hsrc = g_h + (size_t)(cur * 2 + dir) * DH * BB + bt * 128;
        for (int i = tid; i < 8192; i += 256) {
            int k = i >> 5, b4 = (i & 31) << 2;
            float4 v = __ldcg((const float4*)&hsrc[k * BB + b4]);
            *(float4*)&hs[k * 128 + b4] = v;
        }
        __syncthreads();

        // gates tile: [4 batch rows x 4 gate cols] = h @ U^T (slice)
        ull a00 = 0, a01 = 0, a10 = 0, a11 = 0, a20 = 0, a21 = 0, a30 = 0, a31 = 0;
#pragma unroll 4
        for (int k = 0; k < 256; k++) {
            float4 hv = *(float4*)&hs[k * 128 + ty4];
            float4 uv = *(float4*)&Us[k * US_PITCH + tx4];
            ull u01 = pk(uv.x, uv.y), u23 = pk(uv.z, uv.w);
            ull hh;
            hh = pk(hv.x, hv.x); fma2(a00, hh, u01); fma2(a01, hh, u23);
            hh = pk(hv.y, hv.y); fma2(a10, hh, u01); fma2(a11, hh, u23);
            hh = pk(hv.z, hv.z); fma2(a20, hh, u01); fma2(a21, hh, u23);
            hh = pk(hv.w, hv.w); fma2(a30, hh, u01); fma2(a31, hh, u23);
        }

        // epilogue: activations + c update (c lives in registers)
        float hout0, hout1, hout2, hout3;
        {
            float gi, gf, go, gc;
            upk(a00, gi, gf); upk(a01, go, gc);
            gi = sigmoidf_(gi + e0.x); gf = sigmoidf_(gf + e0.y);
            go = sigmoidf_(go + e0.z); gc = tanhf(gc + e0.w);
            c0 = gf * c0 + gi * gc; hout0 = go * tanhf(c0);
        }
        {
            float gi, gf, go, gc;
            upk(a10, gi, gf); upk(a11, go, gc);
            gi = sigmoidf_(gi + e1.x); gf = sigmoidf_(gf + e1.y);
            go = sigmoidf_(go + e1.z); gc = tanhf(gc + e1.w);
            c1 = gf * c1 + gi * gc; hout1 = go * tanhf(c1);
        }
        {
            float gi, gf, go, gc;
            upk(a20, gi, gf); upk(a21, go, gc);
            gi = sigmoidf_(gi + e2.x); gf = sigmoidf_(gf + e2.y);
            go = sigmoidf_(go + e2.z); gc = tanhf(gc + e2.w);
            c2 = gf * c2 + gi * gc; hout2 = go * tanhf(c2);
        }
        {
            float gi, gf, go, gc;
            upk(a30, gi, gf); upk(a31, go, gc);
            gi = sigmoidf_(gi + e3.x); gf = sigmoidf_(gf + e3.y);
            go = sigmoidf_(go + e3.z); gc = tanhf(gc + e3.w);
            c3 = gf * c3 + gi * gc; hout3 = go * tanhf(c3);
        }
        float* hdst = g_h + (size_t)((nxt * 2 + dir) * DH + j) * BB + bbase;
        *(float4*)hdst = make_float4(hout0, hout1, hout2, hout3);

        __syncthreads();  // all threads done with hs + stores issued
        if (t < SS - 1) {
            if (tid == 0) {
                __threadfence();                       // release (CCTL.IVALL scope)
                atomicAdd(&g_bar, 1u);
                unsigned tgt = (unsigned)NBLK_SCAN * (t + 1);
                while (*((volatile unsigned*)&g_bar) < tgt) __nanosleep(64);
                __threadfence();                       // acquire: invalidate stale L1
            }
            __syncthreads();
        }
    }
}

// ---------------- kernel 3: output layer ----------------
__global__ void out_kernel(const float* __restrict__ outW,
                           const float* __restrict__ outb,
                           float* __restrict__ pred) {
    int b = threadIdx.x;  // 256 threads, one batch row each
    float a0 = outb[0], a1 = outb[1];
    const float* hl = g_h + (size_t)(0 * 2 + 0) * DH * BB;  // final h in buf 0
    const float* hr = g_h + (size_t)(0 * 2 + 1) * DH * BB;
#pragma unroll 4
    for (int jj = 0; jj < DH; jj++) {
        float v = hl[jj * BB + b];
        a0 += v * outW[jj];
        a1 += v * outW[512 + jj];
    }
#pragma unroll 4
    for (int jj = 0; jj < DH; jj++) {
        float v = hr[jj * BB + b];
        a0 += v * outW[256 + jj];
        a1 += v * outW[512 + 256 + jj];
    }
    pred[b * 2 + 0] = a0;
    pred[b * 2 + 1] = a1;
}

// ---------------- launch ----------------
extern "C" void kernel_launch(void* const* d_in, const int* in_sizes, int n_in,
                              void* d_out, int out_size) {
    const int*   words = (const int*)d_in[0];
    const float* Emb   = (const float*)d_in[1];
    const float* W     = (const float*)d_in[2];
    const float* U     = (const float*)d_in[3];
    const float* bias  = (const float*)d_in[4];
    const float* outW  = (const float*)d_in[5];
    const float* outb  = (const float*)d_in[6];
    float* pred = (float*)d_out;

    cudaFuncSetAttribute(scan_kernel, cudaFuncAttributeMaxDynamicSharedMemorySize, SCAN_SMEM);

    reset_kernel<<<256, 256>>>(words);
    ew_gemm<<<dim3((NDICT + 63) / 64, NGATE / 64), 256>>>(Emb, W, bias);
    scan_kernel<<<NBLK_SCAN, 256, SCAN_SMEM>>>(U);
    out_kernel<<<1, 256>>>(outW, outb, pred);
}